// round 14
// baseline (speedup 1.0000x reference)
#include <cuda_runtime.h>

#define N_POS 8192
#define N_NEG 4000
#define N_TOT (N_POS + N_POS * N_NEG)   // 32,776,192 = 8192*4001
#define NT4   (N_TOT / 4)               // 8,194,048 vec4 tiles

constexpr int TPB2 = 512;               // pass-2 block size (16 warps)
constexpr int NB2  = 296;               // pass-2 blocks (2/SM, 64KB smem each)
constexpr int NFB  = 64;                // finalize blocks

// Static scratch (allocations forbidden).
__device__ float        g_pos[N_POS];
__device__ unsigned int g_hist [NB2 * N_POS];  // smem-hist dumps (overwritten), 9.7MB
__device__ unsigned int g_hist2[NB2 * N_POS];  // per-block REDG rows (zeroed in p1), 9.7MB
__device__ float        g_psum[NFB];
__device__ unsigned int g_ticket;

// ---------------- Pass 1: scan index (131MB), scatter pos, zero REDG rows ----
// Coalesced: the q-th int4 load of a warp has consecutive lanes. idx reads use
// the default cache policy ON PURPOSE: pass 2 re-reads idx (reversed) and we
// want the tail of idx resident in L2.
constexpr int TPB1  = 256;
constexpr int EPT1  = 32;                      // ints per thread (8 int4 loads)
constexpr int NBLK1 = N_TOT / (TPB1 * EPT1);   // 4001, exact

__global__ __launch_bounds__(TPB1) void k_scatter_pos(
    const int*   __restrict__ idx,
    const float* __restrict__ pv)
{
    const int4* idx4 = reinterpret_cast<const int4*>(idx);
    unsigned int base4 = blockIdx.x * (TPB1 * (EPT1 / 4));  // block's int4 base
    int4 r[8];
#pragma unroll
    for (int q = 0; q < 8; q++)
        r[q] = idx4[base4 + q * TPB1 + threadIdx.x];
#pragma unroll
    for (int q = 0; q < 8; q++) {
        unsigned int e0 = (base4 + q * TPB1 + threadIdx.x) * 4;
        int js[4] = {r[q].x, r[q].y, r[q].z, r[q].w};
#pragma unroll
        for (int k = 0; k < 4; k++) {
            unsigned int j = (unsigned int)js[k];
            if (j < N_POS) g_pos[j] = pv[e0 + k];   // rare: 8192/32.7M
        }
    }
    // Zero the REDG region (2.42M words) + ticket; launch boundary orders it.
    for (unsigned int i = blockIdx.x * TPB1 + threadIdx.x;
         i < (unsigned int)(NB2 * N_POS); i += NBLK1 * TPB1)
        g_hist2[i] = 0u;
    if (blockIdx.x == 0 && threadIdx.x == 0) g_ticket = 0u;
}

// ---------------- Pass 2: smem pos table, 12 ATOMS warps + 4 REDG warps ------
// Rarer-side counting: pos>0 -> count (v >  pos), rank = 1+cnt
//                      pos<=0-> count (v <= pos), rank = 4001-cnt
// REVERSED traversal for L2 reuse of idx from pass 1.
// Warps 12-15 REDG into the block's PRIVATE global row (zero contention);
// warps 0-11 use the smem histogram (ATOMS). Parallel pipes.
__global__ __launch_bounds__(TPB2) void k_count(
    const int*   __restrict__ idx,
    const float* __restrict__ pv)
{
    __shared__ float        spos[N_POS];   // 32KB
    __shared__ unsigned int hist[N_POS];   // 32KB

    for (int i = threadIdx.x; i < N_POS; i += TPB2) {
        spos[i] = g_pos[i];                // coalesced table load
        hist[i] = 0u;
    }
    __syncthreads();

    const bool use_redg = (threadIdx.x >> 5) >= 12;   // 4 of 16 warps
    unsigned int* row2 = g_hist2 + (size_t)blockIdx.x * N_POS;

    const int4*   idx4 = reinterpret_cast<const int4*>(idx);
    const float4* pv4  = reinterpret_cast<const float4*>(pv);

    for (unsigned int u = blockIdx.x * TPB2 + threadIdx.x; u < NT4; u += NB2 * TPB2) {
        const unsigned int t = (NT4 - 1u) - u;           // reversed, coalesced
        int4   a = __ldcs(&idx4[t]);                     // last use of idx
        float4 v = __ldcs(&pv4[t]);                      // single use of pv
        int   js[4] = {a.x, a.y, a.z, a.w};
        float vs[4] = {v.x, v.y, v.z, v.w};
#pragma unroll
        for (int k = 0; k < 4; k++) {
            unsigned int j = (unsigned int)js[k];
            if (j >= N_POS) {
                unsigned int p = (j - N_POS) / N_NEG;   // const-div -> umulhi
                float pos = spos[p];                     // LDS (predicated)
                if ((vs[k] > pos) == (pos > 0.0f)) {     // rarer side (~25%)
                    if (use_redg) atomicAdd(&row2[p], 1u);  // REDG, private row
                    else          atomicAdd(&hist[p], 1u);  // ATOMS, spread-addr
                }
            }
        }
    }
    __syncthreads();

    unsigned int* row = g_hist + (size_t)blockIdx.x * N_POS;
    for (int i = threadIdx.x; i < N_POS; i += TPB2) row[i] = hist[i];  // coalesced
}

// ---------------- Finalize: reduce both regions, smrr, deterministic mean ----
__global__ __launch_bounds__(128) void k_final(float* __restrict__ out)
{
    int p = blockIdx.x * 128 + threadIdx.x;   // 64 x 128 = 8192
    unsigned int cnt = 0;
#pragma unroll 4
    for (int b = 0; b < NB2; b++) {
        cnt += g_hist [(size_t)b * N_POS + p];
        cnt += g_hist2[(size_t)b * N_POS + p];
    }

    float pos = g_pos[p];
    unsigned int rank = (pos > 0.0f) ? (1u + cnt)
                                     : (unsigned int)(N_NEG + 1) - cnt;
    float smrr = 1.0f / (float)rank;
    out[1 + p] = smrr;

    __shared__ float ssum[128];
    ssum[threadIdx.x] = smrr;
    __syncthreads();
    for (int off = 64; off > 0; off >>= 1) {
        if (threadIdx.x < off) ssum[threadIdx.x] += ssum[threadIdx.x + off];
        __syncthreads();
    }
    __shared__ bool last;
    if (threadIdx.x == 0) {
        g_psum[blockIdx.x] = ssum[0];
        __threadfence();
        last = (atomicAdd(&g_ticket, 1u) == NFB - 1);
    }
    __syncthreads();
    if (last && threadIdx.x == 0) {
        float s = 0.0f;
        for (int i = 0; i < NFB; i++) s += g_psum[i];
        out[0] = s / (float)N_POS;
    }
}

extern "C" void kernel_launch(void* const* d_in, const int* in_sizes, int n_in,
                              void* d_out, int out_size)
{
    const float* pv  = (const float*)d_in[0];
    const int*   idx = (const int*)d_in[1];
    float* out = (float*)d_out;
    (void)in_sizes; (void)n_in; (void)out_size;

    k_scatter_pos<<<NBLK1, TPB1>>>(idx, pv);
    k_count<<<NB2, TPB2>>>(idx, pv);
    k_final<<<NFB, 128>>>(out);
}

// round 15
// speedup vs baseline: 1.6971x; 1.6971x over previous
#include <cuda_runtime.h>

#define N_POS 8192
#define N_NEG 4000
#define N_TOT (N_POS + N_POS * N_NEG)   // 32,776,192 = 8192*4001
#define NT4   (N_TOT / 4)               // 8,194,048 vec4 tiles

constexpr int TPB2 = 512;               // pass-2 block size (16 warps)
constexpr int NB2  = 296;               // pass-2 blocks (2/SM, 64KB smem each)
constexpr int NFB  = 64;                // finalize blocks

// Static scratch (allocations forbidden).
__device__ float        g_pos[N_POS];
__device__ unsigned int g_rank[N_POS];  // merged counts (L2-resident, 32KB)
__device__ float        g_psum[NFB];
__device__ unsigned int g_ticket;

// ---------------- Pass 1: scan index (131MB), scatter the 8192 pos values ----
// Coalesced: the q-th int4 load of a warp has consecutive lanes. idx reads use
// the default cache policy ON PURPOSE: pass 2 re-reads idx (reversed) and we
// want the tail of idx resident in L2.
constexpr int TPB1  = 256;
constexpr int EPT1  = 32;                      // ints per thread (8 int4 loads)
constexpr int NBLK1 = N_TOT / (TPB1 * EPT1);   // 4001, exact

__global__ __launch_bounds__(TPB1) void k_scatter_pos(
    const int*   __restrict__ idx,
    const float* __restrict__ pv)
{
    const int4* idx4 = reinterpret_cast<const int4*>(idx);
    unsigned int base4 = blockIdx.x * (TPB1 * (EPT1 / 4));  // block's int4 base
    int4 r[8];
#pragma unroll
    for (int q = 0; q < 8; q++)
        r[q] = idx4[base4 + q * TPB1 + threadIdx.x];
#pragma unroll
    for (int q = 0; q < 8; q++) {
        unsigned int e0 = (base4 + q * TPB1 + threadIdx.x) * 4;
        int js[4] = {r[q].x, r[q].y, r[q].z, r[q].w};
#pragma unroll
        for (int k = 0; k < 4; k++) {
            unsigned int j = (unsigned int)js[k];
            if (j < N_POS) g_pos[j] = pv[e0 + k];   // rare: 8192/32.7M
        }
    }
    // Zero the merged-count array (32KB) + ticket; launch boundary orders it.
    if (blockIdx.x == 0) {
        for (int i = threadIdx.x; i < N_POS; i += TPB1) g_rank[i] = 0u;
        if (threadIdx.x == 0) g_ticket = 0u;
    }
}

// ---------------- Pass 2: smem pos table + smem histograms -------------------
// Rarer-side counting: pos>0 -> count (v >  pos), rank = 1+cnt
//                      pos<=0-> count (v <= pos), rank = 4001-cnt
// REVERSED traversal: pass 1 streamed idx low->high, so L2 holds the tail of
// idx; reading high->low turns a large fraction of idx reads into L2 hits.
// Epilogue: sparse REDG merge of the block's histogram into g_rank (32KB,
// L2-resident) -- 2.4M total adds, <=296 hits/address, staggered in time.
__global__ __launch_bounds__(TPB2) void k_count(
    const int*   __restrict__ idx,
    const float* __restrict__ pv)
{
    __shared__ float        spos[N_POS];   // 32KB
    __shared__ unsigned int hist[N_POS];   // 32KB

    for (int i = threadIdx.x; i < N_POS; i += TPB2) {
        spos[i] = g_pos[i];                // coalesced table load
        hist[i] = 0u;
    }
    __syncthreads();

    const int4*   idx4 = reinterpret_cast<const int4*>(idx);
    const float4* pv4  = reinterpret_cast<const float4*>(pv);

    for (unsigned int u = blockIdx.x * TPB2 + threadIdx.x; u < NT4; u += NB2 * TPB2) {
        const unsigned int t = (NT4 - 1u) - u;           // reversed, coalesced
        int4   a = __ldcs(&idx4[t]);                     // last use of idx
        float4 v = __ldcs(&pv4[t]);                      // single use of pv
        int   js[4] = {a.x, a.y, a.z, a.w};
        float vs[4] = {v.x, v.y, v.z, v.w};
#pragma unroll
        for (int k = 0; k < 4; k++) {
            unsigned int j = (unsigned int)js[k];
            if (j >= N_POS) {
                unsigned int p = (j - N_POS) / N_NEG;   // const-div -> umulhi
                float pos = spos[p];                     // LDS (predicated)
                if ((vs[k] > pos) == (pos > 0.0f)) {     // rarer side (~25%)
                    atomicAdd(&hist[p], 1u);             // ATOMS, spread-addr
                }
            }
        }
    }
    __syncthreads();

    // Sparse flush straight into the merged array (skip zero rows).
    for (int i = threadIdx.x; i < N_POS; i += TPB2) {
        unsigned int c = hist[i];
        if (c) atomicAdd(&g_rank[i], c);   // REDG, coalesced, low contention
    }
}

// ---------------- Finalize: ranks -> smrr, deterministic mean ----------------
__global__ __launch_bounds__(128) void k_final(float* __restrict__ out)
{
    int p = blockIdx.x * 128 + threadIdx.x;   // 64 x 128 = 8192
    unsigned int cnt = g_rank[p];

    float pos = g_pos[p];
    unsigned int rank = (pos > 0.0f) ? (1u + cnt)
                                     : (unsigned int)(N_NEG + 1) - cnt;
    float smrr = 1.0f / (float)rank;
    out[1 + p] = smrr;

    __shared__ float ssum[128];
    ssum[threadIdx.x] = smrr;
    __syncthreads();
    for (int off = 64; off > 0; off >>= 1) {
        if (threadIdx.x < off) ssum[threadIdx.x] += ssum[threadIdx.x + off];
        __syncthreads();
    }
    __shared__ bool last;
    if (threadIdx.x == 0) {
        g_psum[blockIdx.x] = ssum[0];
        __threadfence();
        last = (atomicAdd(&g_ticket, 1u) == NFB - 1);
    }
    __syncthreads();
    if (last && threadIdx.x == 0) {
        float s = 0.0f;
        for (int i = 0; i < NFB; i++) s += g_psum[i];
        out[0] = s / (float)N_POS;
    }
}

extern "C" void kernel_launch(void* const* d_in, const int* in_sizes, int n_in,
                              void* d_out, int out_size)
{
    const float* pv  = (const float*)d_in[0];
    const int*   idx = (const int*)d_in[1];
    float* out = (float*)d_out;
    (void)in_sizes; (void)n_in; (void)out_size;

    k_scatter_pos<<<NBLK1, TPB1>>>(idx, pv);
    k_count<<<NB2, TPB2>>>(idx, pv);
    k_final<<<NFB, 128>>>(out);
}